// round 14
// baseline (speedup 1.0000x reference)
#include <cuda_runtime.h>
#include <cstdint>

#define BB 4
#define TT 256
#define LL 216
#define EPC 12
#define EROOT 12
#define EQUAL 16
#define KK 41
#define W_NM 0.1f
#define W_ADV 0.001f

// device scratch (no cudaMalloc allowed)
__device__ float g_cs[BB][TT + 1][48];                 // prefix sums, channel-innermost
__device__ float g_h[BB][KK][LL];                      // folded harmony coefficients, k-major
__device__ __align__(16) float g_Dhi[BB][TT + 1][LL];  // D = cs @ h, compensated hi
__device__ __align__(16) float g_Dlo[BB][TT + 1][LL];  // compensation (lo) part

// ---------------- K0a: prefix scans over t, one (b,channel) per block ----------------
__global__ void prep_kernel(const float* __restrict__ apc,
                            const float* __restrict__ aroot,
                            const float* __restrict__ aqual,
                            const float* __restrict__ iroot,
                            const float* __restrict__ iqual,
                            int b0) {
    __shared__ float wsum[8];
    int ch = blockIdx.x;          // 0..40
    int b  = b0 + blockIdx.y;
    int t  = threadIdx.x;
    int w  = t >> 5, lane = t & 31;
    float x;
    if (ch < 12) {
        x = apc[(b * TT + t) * EPC + ch];
    } else if (ch < 24) {
        int j = ch - 12;
        x = aroot[(b * TT + t) * EROOT + j] - W_ADV * iroot[(b * TT + t) * EROOT + j];
    } else if (ch < 40) {
        int j = ch - 24;
        x = aqual[(b * TT + t) * EQUAL + j] - W_ADV * iqual[(b * TT + t) * EQUAL + j];
    } else {
        x = 1.0f;  // channel 40 carries the -W_NM*Hs term (segment mean == 1)
    }
    float v = x;
    #pragma unroll
    for (int off = 1; off < 32; off <<= 1) {
        float n = __shfl_up_sync(0xFFFFFFFFu, v, off);
        if (lane >= off) v += n;
    }
    if (lane == 31) wsum[w] = v;
    __syncthreads();
    if (t < 8) {
        float s = wsum[t];
        #pragma unroll
        for (int off = 1; off < 8; off <<= 1) {
            float n = __shfl_up_sync(0x000000FFu, s, off);
            if (t >= off) s += n;
        }
        wsum[t] = s;
    }
    __syncthreads();
    float base = (w > 0) ? wsum[w - 1] : 0.0f;
    g_cs[b][t + 1][ch] = v + base;
    if (t == 0) g_cs[b][0][ch] = 0.0f;
}

// ---------------- K0b: h-fold with coalesced smem staging (standalone) ----------------
__global__ void hfold_kernel(const float* __restrict__ hpc,
                             const float* __restrict__ hroot,
                             const float* __restrict__ hqual,
                             const int* __restrict__ pc_only,
                             int b0) {
    __shared__ float sh_pc[LL * EPC];
    __shared__ float sh_root[LL * EROOT];
    __shared__ float sh_qual[LL * EQUAL];
    int b = b0 + blockIdx.x;
    int tid = threadIdx.x;
    for (int i = tid; i < LL * EPC; i += 256) sh_pc[i] = hpc[b * LL * EPC + i];
    for (int i = tid; i < LL * EROOT; i += 256) sh_root[i] = hroot[b * LL * EROOT + i];
    for (int i = tid; i < LL * EQUAL; i += 256) sh_qual[i] = hqual[b * LL * EQUAL + i];
    __syncthreads();
    int l = tid;
    if (l >= LL) return;
    int po = pc_only ? pc_only[0] : 0;
    float hs = 0.0f;
    #pragma unroll
    for (int j = 0; j < 12; j++) hs += sh_pc[l * EPC + j];
    float coef = (1.0f + 2.0f * W_NM) - W_ADV / hs;
    #pragma unroll
    for (int j = 0; j < 12; j++) g_h[b][j][l] = fmaf(sh_pc[l * EPC + j], coef, -W_NM);
    #pragma unroll
    for (int j = 0; j < 12; j++) g_h[b][12 + j][l] = po ? 0.0f : sh_root[l * EROOT + j];
    #pragma unroll
    for (int j = 0; j < 16; j++) g_h[b][24 + j][l] = po ? 0.0f : sh_qual[l * EQUAL + j];
    g_h[b][40][l] = -W_NM * hs;
}

// ---------------- K1: D = cs @ h (g_h coalesced), fp32 compensated accumulation ----------------
__global__ __launch_bounds__(224)
void d_kernel(int b0) {
    __shared__ float cs_s[KK];
    int t = blockIdx.x;           // 0..256
    int b = b0 + blockIdx.y;
    int l = threadIdx.x;          // 0..223
    if (l < KK) cs_s[l] = g_cs[b][t][l];
    __syncthreads();
    if (l >= LL) return;

    float s = 0.0f, c = 0.0f;
    #pragma unroll
    for (int k = 0; k < KK; k++) {
        float a  = cs_s[k];
        float h  = g_h[b][k][l];
        float p  = a * h;
        float ep = fmaf(a, h, -p);       // exact product error
        float tt = s + p;                // TwoSum
        float z  = tt - s;
        float e2 = (s - (tt - z)) + (p - z);
        s = tt;
        c += ep + e2;
    }
    g_Dhi[b][t][l] = s;
    g_Dlo[b][t][l] = c;
}

// ---------------- main: out[b,s,e,l] = (D[e+1,l]-D[s,l]) * inv_len (R13 exact, +b0) ----------------
#define SM_LOS 1728
#define SM_HIE 3456
#define SM_LOE 10368
#define SM_INV 17280
#define SM_FLOATS 17536   // 70144 bytes

__global__ __launch_bounds__(256, 2)
void main_kernel(float* __restrict__ out, int b0) {
    extern __shared__ float sm[];
    const int tid = threadIdx.x;
    const int st = blockIdx.x, et = blockIdx.y, b = b0 + blockIdx.z;
    const int s0 = st * 8, e0 = et * 32;

    const float* __restrict__ Dhi = &g_Dhi[b][0][0];
    const float* __restrict__ Dlo = &g_Dlo[b][0][0];

    // stage 40 D-rows (8 s-rows, 32 e-rows at t=e+1) as hi/lo
    for (int idx = tid; idx < 40 * 54; idx += 256) {
        int row = idx / 54, c = idx - row * 54;
        int t = (row < 8) ? (s0 + row) : (e0 + (row - 8) + 1);
        float4 vh = *(const float4*)(Dhi + t * LL + c * 4);
        float4 vl = *(const float4*)(Dlo + t * LL + c * 4);
        int dh = (row < 8) ? (row * LL) : (SM_HIE + (row - 8) * LL);
        int dl = dh + ((row < 8) ? SM_LOS : (SM_LOE - SM_HIE));
        *(float4*)(sm + dh + c * 4) = vh;
        *(float4*)(sm + dl + c * 4) = vl;
    }
    // inv table with validity baked in (inv = 0 for e < s)
    {
        int s = tid >> 5, e = tid & 31;
        int len = (e0 + e) - (s0 + s) + 1;
        sm[SM_INV + tid] = (len >= 1) ? __fdividef(1.0f, (float)len) : 0.0f;
    }
    __syncthreads();

    const int c = tid & 63;
    const int g = tid >> 6;
    if (c >= 54) return;

    const float4* __restrict__ hiS4 = (const float4*)sm;
    const float4* __restrict__ loS4 = (const float4*)(sm + SM_LOS);
    const float4* __restrict__ hiE4 = (const float4*)(sm + SM_HIE);
    const float4* __restrict__ loE4 = (const float4*)(sm + SM_LOE);
    const float*  __restrict__ invt = sm + SM_INV;

    // register-block the E tile: read once, reuse across all 8 s
    float4 heR[8], leR[8];
    #pragma unroll
    for (int eg = 0; eg < 8; eg++) {
        int e = g * 8 + eg;
        heR[eg] = hiE4[e * 54 + c];
        leR[eg] = loE4[e * 54 + c];
    }

    float* base = out + ((size_t)(b * 65536 + s0 * 256 + e0 + g * 8)) * LL + c * 4;

    #pragma unroll 1
    for (int s = 0; s < 8; s++) {
        float4 hs = hiS4[s * 54 + c];
        float4 ls = loS4[s * 54 + c];
        float* ps = base + (size_t)s * (256 * LL);
        #pragma unroll
        for (int eg = 0; eg < 8; eg++) {
            float inv = invt[s * 32 + g * 8 + eg];
            float4 he = heR[eg];
            float4 le = leR[eg];
            float4 v;
            v.x = ((he.x - hs.x) + (le.x - ls.x)) * inv;
            v.y = ((he.y - hs.y) + (le.y - ls.y)) * inv;
            v.z = ((he.z - hs.z) + (le.z - ls.z)) * inv;
            v.w = ((he.w - hs.w) + (le.w - ls.w)) * inv;
            __stcs((float4*)(ps + eg * LL), v);   // streaming store: write-once output
        }
    }
}

extern "C" void kernel_launch(void* const* d_in, const int* in_sizes, int n_in,
                              void* d_out, int out_size) {
    const float* apc   = (const float*)d_in[0];
    const float* aroot = (const float*)d_in[1];
    const float* aqual = (const float*)d_in[2];
    // d_in[3] = inactive_pc: unused by the reference
    const float* iroot = (const float*)d_in[4];
    const float* iqual = (const float*)d_in[5];
    const float* hpc   = (const float*)d_in[6];
    const float* hroot = (const float*)d_in[7];
    const float* hqual = (const float*)d_in[8];
    const int*   pco   = (n_in > 9) ? (const int*)d_in[9] : nullptr;

    static bool init_done = false;
    static cudaStream_t s1;
    static cudaEvent_t eFork, eJoin;
    if (!init_done) {
        cudaFuncSetAttribute(main_kernel, cudaFuncAttributeMaxDynamicSharedMemorySize,
                             SM_FLOATS * 4);
        cudaStreamCreateWithFlags(&s1, cudaStreamNonBlocking);
        cudaEventCreateWithFlags(&eFork, cudaEventDisableTiming);
        cudaEventCreateWithFlags(&eJoin, cudaEventDisableTiming);
        init_done = true;
    }

    // fork: side stream computes the prelude for batches 1..3 while the
    // default stream does batch 0's prelude and main(b0).
    cudaEventRecord(eFork, 0);
    cudaStreamWaitEvent(s1, eFork, 0);

    // side stream: batches 1..3
    prep_kernel<<<dim3(KK, 3), 256, 0, s1>>>(apc, aroot, aqual, iroot, iqual, 1);
    hfold_kernel<<<3, 256, 0, s1>>>(hpc, hroot, hqual, pco, 1);
    d_kernel<<<dim3(TT + 1, 3), 224, 0, s1>>>(1);
    cudaEventRecord(eJoin, s1);

    // default stream: batch 0 prelude + main(b0)
    prep_kernel<<<dim3(KK, 1), 256>>>(apc, aroot, aqual, iroot, iqual, 0);
    hfold_kernel<<<1, 256>>>(hpc, hroot, hqual, pco, 0);
    d_kernel<<<dim3(TT + 1, 1), 224>>>(0);
    main_kernel<<<dim3(32, 8, 1), 256, SM_FLOATS * 4>>>((float*)d_out, 0);

    // join, then main for batches 1..3
    cudaStreamWaitEvent(0, eJoin, 0);
    main_kernel<<<dim3(32, 8, 3), 256, SM_FLOATS * 4>>>((float*)d_out, 1);
}

// round 16
// speedup vs baseline: 1.3528x; 1.3528x over previous
#include <cuda_runtime.h>
#include <cstdint>

#define BB 4
#define TT 256
#define LL 216
#define EPC 12
#define EROOT 12
#define EQUAL 16
#define KK 41
#define W_NM 0.1f
#define W_ADV 0.001f

// device scratch (no cudaMalloc allowed)
__device__ float g_cs[BB][TT + 1][48];                 // prefix sums, channel-innermost
__device__ float g_h[BB][KK][LL];                      // folded harmony coefficients, k-major
__device__ __align__(16) float g_D[BB][TT + 1][LL];    // D = cs @ h (best fp32, compensated internally)

// ---------------- K0: scans (blocks 0..163) + h-fold (blocks 164..167) — R6 exact ----------------
__global__ void prep_kernel(const float* __restrict__ apc,
                            const float* __restrict__ aroot,
                            const float* __restrict__ aqual,
                            const float* __restrict__ iroot,
                            const float* __restrict__ iqual,
                            const float* __restrict__ hpc,
                            const float* __restrict__ hroot,
                            const float* __restrict__ hqual,
                            const int* __restrict__ pc_only) {
    __shared__ float wsum[8];
    int bx = blockIdx.x;
    if (bx < KK * BB) {
        int ch = bx % KK;
        int b  = bx / KK;
        int t  = threadIdx.x;
        int w  = t >> 5, lane = t & 31;
        float x;
        if (ch < 12) {
            x = apc[(b * TT + t) * EPC + ch];
        } else if (ch < 24) {
            int j = ch - 12;
            x = aroot[(b * TT + t) * EROOT + j] - W_ADV * iroot[(b * TT + t) * EROOT + j];
        } else if (ch < 40) {
            int j = ch - 24;
            x = aqual[(b * TT + t) * EQUAL + j] - W_ADV * iqual[(b * TT + t) * EQUAL + j];
        } else {
            x = 1.0f;  // channel 40 carries the -W_NM*Hs term (segment mean == 1)
        }
        float v = x;
        #pragma unroll
        for (int off = 1; off < 32; off <<= 1) {
            float n = __shfl_up_sync(0xFFFFFFFFu, v, off);
            if (lane >= off) v += n;
        }
        if (lane == 31) wsum[w] = v;
        __syncthreads();
        if (t < 8) {
            float s = wsum[t];
            #pragma unroll
            for (int off = 1; off < 8; off <<= 1) {
                float n = __shfl_up_sync(0x000000FFu, s, off);
                if (t >= off) s += n;
            }
            wsum[t] = s;
        }
        __syncthreads();
        float base = (w > 0) ? wsum[w - 1] : 0.0f;
        g_cs[b][t + 1][ch] = v + base;
        if (t == 0) g_cs[b][0][ch] = 0.0f;
    } else {
        int b = bx - KK * BB;
        int l = threadIdx.x;
        if (l >= LL) return;
        int po = pc_only ? pc_only[0] : 0;
        float hv[12];
        float hs = 0.0f;
        #pragma unroll
        for (int j = 0; j < 12; j++) { hv[j] = hpc[(b * LL + l) * EPC + j]; hs += hv[j]; }
        float coef = (1.0f + 2.0f * W_NM) - W_ADV / hs;
        #pragma unroll
        for (int j = 0; j < 12; j++) g_h[b][j][l] = fmaf(hv[j], coef, -W_NM);
        #pragma unroll
        for (int j = 0; j < 12; j++) g_h[b][12 + j][l] = po ? 0.0f : hroot[(b * LL + l) * EROOT + j];
        #pragma unroll
        for (int j = 0; j < 16; j++) g_h[b][24 + j][l] = po ? 0.0f : hqual[(b * LL + l) * EQUAL + j];
        g_h[b][40][l] = -W_NM * hs;
    }
}

// ---------------- K1: D = cs @ h, compensated internally, stored as best fp32 ----------------
__global__ __launch_bounds__(224)
void d_kernel() {
    __shared__ float cs_s[KK];
    int t = blockIdx.x;   // 0..256
    int b = blockIdx.y;
    int l = threadIdx.x;  // 0..223
    if (l < KK) cs_s[l] = g_cs[b][t][l];
    __syncthreads();
    if (l >= LL) return;

    float s = 0.0f, c = 0.0f;
    #pragma unroll
    for (int k = 0; k < KK; k++) {
        float a  = cs_s[k];
        float h  = g_h[b][k][l];
        float p  = a * h;
        float ep = fmaf(a, h, -p);       // exact product error
        float tt = s + p;                // TwoSum
        float z  = tt - s;
        float e2 = (s - (tt - z)) + (p - z);
        s = tt;
        c += ep + e2;
    }
    g_D[b][t][l] = s + c;   // correctly-rounded-to-working-precision sum
}

// ---------------- main: out[b,s,e,l] = (D[e+1,l]-D[s,l]) * inv_len ----------------
// fp32-only D table: half the staging traffic, smem 35.6 KB -> occ 4.
// tile = 8 s x 32 e x full L; 256 threads; thread: chunk c=tid&63 (c<54), e-group g=tid>>6
// smem floats: dS[8*216] | dE[32*216] | inv[256]
#define SM_DE  1728
#define SM_INV 8640
#define SM_FLOATS 8896   // 35584 bytes

__global__ __launch_bounds__(256, 4)
void main_kernel(float* __restrict__ out) {
    extern __shared__ float sm[];
    const int tid = threadIdx.x;
    const int st = blockIdx.x, et = blockIdx.y, b = blockIdx.z;
    const int s0 = st * 8, e0 = et * 32;

    const float* __restrict__ D = &g_D[b][0][0];

    // stage 40 D-rows (8 s-rows, 32 e-rows at t=e+1)
    for (int idx = tid; idx < 40 * 54; idx += 256) {
        int row = idx / 54, c = idx - row * 54;
        int t = (row < 8) ? (s0 + row) : (e0 + (row - 8) + 1);
        float4 v = *(const float4*)(D + t * LL + c * 4);
        int d = (row < 8) ? (row * LL) : (SM_DE + (row - 8) * LL);
        *(float4*)(sm + d + c * 4) = v;
    }
    // inv table with validity baked in (inv = 0 for e < s)
    {
        int s = tid >> 5, e = tid & 31;
        int len = (e0 + e) - (s0 + s) + 1;
        sm[SM_INV + tid] = (len >= 1) ? __fdividef(1.0f, (float)len) : 0.0f;
    }
    __syncthreads();

    const int c = tid & 63;
    const int g = tid >> 6;
    if (c >= 54) return;

    const float4* __restrict__ dS4 = (const float4*)sm;
    const float4* __restrict__ dE4 = (const float4*)(sm + SM_DE);
    const float*  __restrict__ invt = sm + SM_INV;

    // register-block the E tile: read once, reuse across all 8 s
    float4 heR[8];
    #pragma unroll
    for (int eg = 0; eg < 8; eg++) heR[eg] = dE4[(g * 8 + eg) * 54 + c];

    float* base = out + ((size_t)(b * 65536 + s0 * 256 + e0 + g * 8)) * LL + c * 4;

    #pragma unroll 1
    for (int s = 0; s < 8; s++) {
        float4 hs = dS4[s * 54 + c];
        float* ps = base + (size_t)s * (256 * LL);
        #pragma unroll
        for (int eg = 0; eg < 8; eg++) {
            float inv = invt[s * 32 + g * 8 + eg];
            float4 he = heR[eg];
            float4 v;
            v.x = (he.x - hs.x) * inv;
            v.y = (he.y - hs.y) * inv;
            v.z = (he.z - hs.z) * inv;
            v.w = (he.w - hs.w) * inv;
            __stcs((float4*)(ps + eg * LL), v);   // streaming store: write-once output
        }
    }
}

extern "C" void kernel_launch(void* const* d_in, const int* in_sizes, int n_in,
                              void* d_out, int out_size) {
    const float* apc   = (const float*)d_in[0];
    const float* aroot = (const float*)d_in[1];
    const float* aqual = (const float*)d_in[2];
    // d_in[3] = inactive_pc: unused by the reference
    const float* iroot = (const float*)d_in[4];
    const float* iqual = (const float*)d_in[5];
    const float* hpc   = (const float*)d_in[6];
    const float* hroot = (const float*)d_in[7];
    const float* hqual = (const float*)d_in[8];
    const int*   pco   = (n_in > 9) ? (const int*)d_in[9] : nullptr;

    static bool attr_done = false;
    if (!attr_done) {
        cudaFuncSetAttribute(main_kernel, cudaFuncAttributeMaxDynamicSharedMemorySize,
                             SM_FLOATS * 4);
        attr_done = true;
    }

    prep_kernel<<<KK * BB + BB, 256>>>(apc, aroot, aqual, iroot, iqual,
                                       hpc, hroot, hqual, pco);
    d_kernel<<<dim3(TT + 1, BB), 224>>>();
    main_kernel<<<dim3(32, 8, BB), 256, SM_FLOATS * 4>>>((float*)d_out);
}

// round 17
// speedup vs baseline: 1.3581x; 1.0039x over previous
#include <cuda_runtime.h>
#include <cstdint>

#define BB 4
#define TT 256
#define LL 216
#define EPC 12
#define EROOT 12
#define EQUAL 16
#define KK 41
#define W_NM 0.1f
#define W_ADV 0.001f

// device scratch (no cudaMalloc allowed)
__device__ float g_cs[BB][TT + 1][48];                 // prefix sums, channel-innermost
__device__ float g_h[BB][KK][LL];                      // folded harmony coefficients, k-major
__device__ __align__(16) float g_D[BB][TT + 1][LL];    // D = cs @ h (best fp32, compensated internally)

// ---------------- K0: batch-interleaved scans (blocks 0..40) + h-fold (41..44) ----------------
// One block per channel; each thread scans all 4 batches with interleaved shfl chains (ILP
// hides SHFL latency; 4 independent LDGs give MLP=4 on the cold input reads).
__global__ void prep_kernel(const float* __restrict__ apc,
                            const float* __restrict__ aroot,
                            const float* __restrict__ aqual,
                            const float* __restrict__ iroot,
                            const float* __restrict__ iqual,
                            const float* __restrict__ hpc,
                            const float* __restrict__ hroot,
                            const float* __restrict__ hqual,
                            const int* __restrict__ pc_only) {
    int bx = blockIdx.x;
    if (bx < KK) {
        __shared__ float wsum[BB][8];
        int ch = bx;
        int t  = threadIdx.x;
        int w  = t >> 5, lane = t & 31;

        float v[BB];
        #pragma unroll
        for (int b = 0; b < BB; b++) {
            float x;
            if (ch < 12) {
                x = apc[(b * TT + t) * EPC + ch];
            } else if (ch < 24) {
                int j = ch - 12;
                x = aroot[(b * TT + t) * EROOT + j] - W_ADV * iroot[(b * TT + t) * EROOT + j];
            } else if (ch < 40) {
                int j = ch - 24;
                x = aqual[(b * TT + t) * EQUAL + j] - W_ADV * iqual[(b * TT + t) * EQUAL + j];
            } else {
                x = 1.0f;  // channel 40 carries the -W_NM*Hs term (segment mean == 1)
            }
            v[b] = x;
        }
        // 4 interleaved inclusive warp scans
        #pragma unroll
        for (int off = 1; off < 32; off <<= 1) {
            #pragma unroll
            for (int b = 0; b < BB; b++) {
                float n = __shfl_up_sync(0xFFFFFFFFu, v[b], off);
                if (lane >= off) v[b] += n;
            }
        }
        if (lane == 31) {
            #pragma unroll
            for (int b = 0; b < BB; b++) wsum[b][w] = v[b];
        }
        __syncthreads();
        if (t < 32) {
            int b = t >> 3, i = t & 7;
            float s = wsum[b][i];
            #pragma unroll
            for (int off = 1; off < 8; off <<= 1) {
                float n = __shfl_up_sync(0xFFFFFFFFu, s, off, 8);  // width-8 segmented
                if (i >= off) s += n;
            }
            wsum[b][i] = s;
        }
        __syncthreads();
        #pragma unroll
        for (int b = 0; b < BB; b++) {
            float base = (w > 0) ? wsum[b][w - 1] : 0.0f;
            g_cs[b][t + 1][ch] = v[b] + base;
        }
        if (t == 0) {
            #pragma unroll
            for (int b = 0; b < BB; b++) g_cs[b][0][ch] = 0.0f;
        }
    } else {
        int b = bx - KK;
        int l = threadIdx.x;
        if (l >= LL) return;
        int po = pc_only ? pc_only[0] : 0;
        float hv[12];
        float hs = 0.0f;
        #pragma unroll
        for (int j = 0; j < 12; j++) { hv[j] = hpc[(b * LL + l) * EPC + j]; hs += hv[j]; }
        float coef = (1.0f + 2.0f * W_NM) - W_ADV / hs;
        #pragma unroll
        for (int j = 0; j < 12; j++) g_h[b][j][l] = fmaf(hv[j], coef, -W_NM);
        #pragma unroll
        for (int j = 0; j < 12; j++) g_h[b][12 + j][l] = po ? 0.0f : hroot[(b * LL + l) * EROOT + j];
        #pragma unroll
        for (int j = 0; j < 16; j++) g_h[b][24 + j][l] = po ? 0.0f : hqual[(b * LL + l) * EQUAL + j];
        g_h[b][40][l] = -W_NM * hs;
    }
}

// ---------------- K1: D = cs @ h, compensated internally, stored as best fp32 ----------------
__global__ __launch_bounds__(224)
void d_kernel() {
    __shared__ float cs_s[KK];
    int t = blockIdx.x;   // 0..256
    int b = blockIdx.y;
    int l = threadIdx.x;  // 0..223
    if (l < KK) cs_s[l] = g_cs[b][t][l];
    __syncthreads();
    if (l >= LL) return;

    float s = 0.0f, c = 0.0f;
    #pragma unroll
    for (int k = 0; k < KK; k++) {
        float a  = cs_s[k];
        float h  = g_h[b][k][l];
        float p  = a * h;
        float ep = fmaf(a, h, -p);       // exact product error
        float tt = s + p;                // TwoSum
        float z  = tt - s;
        float e2 = (s - (tt - z)) + (p - z);
        s = tt;
        c += ep + e2;
    }
    g_D[b][t][l] = s + c;   // correctly-rounded-to-working-precision sum
}

// ---------------- main: out[b,s,e,l] = (D[e+1,l]-D[s,l]) * inv_len (R16 exact) ----------------
// fp32-only D table; tile = 8 s x 32 e x full L; 256 threads; occ 4; __stcs stores.
// smem floats: dS[8*216] | dE[32*216] | inv[256]
#define SM_DE  1728
#define SM_INV 8640
#define SM_FLOATS 8896   // 35584 bytes

__global__ __launch_bounds__(256, 4)
void main_kernel(float* __restrict__ out) {
    extern __shared__ float sm[];
    const int tid = threadIdx.x;
    const int st = blockIdx.x, et = blockIdx.y, b = blockIdx.z;
    const int s0 = st * 8, e0 = et * 32;

    const float* __restrict__ D = &g_D[b][0][0];

    // stage 40 D-rows (8 s-rows, 32 e-rows at t=e+1)
    for (int idx = tid; idx < 40 * 54; idx += 256) {
        int row = idx / 54, c = idx - row * 54;
        int t = (row < 8) ? (s0 + row) : (e0 + (row - 8) + 1);
        float4 v = *(const float4*)(D + t * LL + c * 4);
        int d = (row < 8) ? (row * LL) : (SM_DE + (row - 8) * LL);
        *(float4*)(sm + d + c * 4) = v;
    }
    // inv table with validity baked in (inv = 0 for e < s)
    {
        int s = tid >> 5, e = tid & 31;
        int len = (e0 + e) - (s0 + s) + 1;
        sm[SM_INV + tid] = (len >= 1) ? __fdividef(1.0f, (float)len) : 0.0f;
    }
    __syncthreads();

    const int c = tid & 63;
    const int g = tid >> 6;
    if (c >= 54) return;

    const float4* __restrict__ dS4 = (const float4*)sm;
    const float4* __restrict__ dE4 = (const float4*)(sm + SM_DE);
    const float*  __restrict__ invt = sm + SM_INV;

    // register-block the E tile: read once, reuse across all 8 s
    float4 heR[8];
    #pragma unroll
    for (int eg = 0; eg < 8; eg++) heR[eg] = dE4[(g * 8 + eg) * 54 + c];

    float* base = out + ((size_t)(b * 65536 + s0 * 256 + e0 + g * 8)) * LL + c * 4;

    #pragma unroll 1
    for (int s = 0; s < 8; s++) {
        float4 hs = dS4[s * 54 + c];
        float* ps = base + (size_t)s * (256 * LL);
        #pragma unroll
        for (int eg = 0; eg < 8; eg++) {
            float inv = invt[s * 32 + g * 8 + eg];
            float4 he = heR[eg];
            float4 v;
            v.x = (he.x - hs.x) * inv;
            v.y = (he.y - hs.y) * inv;
            v.z = (he.z - hs.z) * inv;
            v.w = (he.w - hs.w) * inv;
            __stcs((float4*)(ps + eg * LL), v);   // streaming store: write-once output
        }
    }
}

extern "C" void kernel_launch(void* const* d_in, const int* in_sizes, int n_in,
                              void* d_out, int out_size) {
    const float* apc   = (const float*)d_in[0];
    const float* aroot = (const float*)d_in[1];
    const float* aqual = (const float*)d_in[2];
    // d_in[3] = inactive_pc: unused by the reference
    const float* iroot = (const float*)d_in[4];
    const float* iqual = (const float*)d_in[5];
    const float* hpc   = (const float*)d_in[6];
    const float* hroot = (const float*)d_in[7];
    const float* hqual = (const float*)d_in[8];
    const int*   pco   = (n_in > 9) ? (const int*)d_in[9] : nullptr;

    static bool attr_done = false;
    if (!attr_done) {
        cudaFuncSetAttribute(main_kernel, cudaFuncAttributeMaxDynamicSharedMemorySize,
                             SM_FLOATS * 4);
        attr_done = true;
    }

    prep_kernel<<<KK + BB, 256>>>(apc, aroot, aqual, iroot, iqual,
                                  hpc, hroot, hqual, pco);
    d_kernel<<<dim3(TT + 1, BB), 224>>>();
    main_kernel<<<dim3(32, 8, BB), 256, SM_FLOATS * 4>>>((float*)d_out);
}